// round 17
// baseline (speedup 1.0000x reference)
#include <cuda_runtime.h>
#include <cuda_fp16.h>
#include <cstdint>

#define TT 128
#define FF 63
#define PP 64
#define NT 512
#define MR 64

// fp16 weight image: [ks 0..11][s 0..7][j 0..7][lane 0..31] -> uint2
//   k: reg0 = ks*16 + 2c,+1 ; reg1 = +8  (c = lane&3)
//   col v = lane>>2; jl = s*16 + 4*(j&3) + (v>>1), type = (j>>2)*2 + (v&1)
__device__ uint2 g_WimgH[12 * 8 * 8 * 32];
__device__ float g_bias[512];

static __device__ __forceinline__ float th_(float x) {
    float r; asm("tanh.approx.f32 %0, %1;" : "=f"(r) : "f"(x)); return r;
}
static __device__ __forceinline__ float sg_(float x) { return fmaf(0.5f, th_(0.5f * x), 0.5f); }

// half-element offset of (row, k) inside the A fragment image (64 rows)
static __device__ __forceinline__ int frag_off_h(int row, int k) {
    int mt = row >> 4, tr = row & 15, ks = k >> 4, kc = k & 15;
    int lane = ((tr & 7) << 2) | ((kc & 7) >> 1);
    int reg  = ((tr >> 3) & 1) | ((kc >> 3) << 1);
    return (((mt * 12 + ks) * 32 + lane) * 4 + reg) * 2 + (kc & 1);
}

static __device__ __forceinline__ void mma16(float* d, uint4 a, uint2 b) {
    asm volatile("mma.sync.aligned.m16n8k16.row.col.f32.f16.f16.f32 "
        "{%0,%1,%2,%3}, {%4,%5,%6,%7}, {%8,%9}, {%0,%1,%2,%3};"
        : "+f"(d[0]), "+f"(d[1]), "+f"(d[2]), "+f"(d[3])
        : "r"(a.x), "r"(a.y), "r"(a.z), "r"(a.w), "r"(b.x), "r"(b.y));
}

static __device__ __forceinline__ float wfold(const float* Wih, const float* Whh,
                                              const float* Wout, int g, int k) {
    return (k < 64) ? Wih[g * 64 + k]
                    : Whh[g * 128 + (k - 64)] + Wih[g * 64] * Wout[k - 64];
}

__global__ void setup_kernel(const float* __restrict__ Wih, const float* __restrict__ Whh,
                             const float* __restrict__ bih, const float* __restrict__ bhh,
                             const float* __restrict__ Wout, const float* __restrict__ bout) {
    int idx = blockIdx.x * blockDim.x + threadIdx.x;   // 0..24575
    if (idx < 24576) {
        int lane = idx & 31, j = (idx >> 5) & 7, s = (idx >> 8) & 7, ks = idx >> 11;
        int tpr = lane >> 2, c = lane & 3;
        int jl   = s * 16 + 4 * (j & 3) + (tpr >> 1);
        int type = (j >> 2) * 2 + (tpr & 1);
        int g = type * 128 + jl;
        int kb = ks * 16;
        __half2 lo = __floats2half2_rn(wfold(Wih, Whh, Wout, g, kb + 2 * c),
                                       wfold(Wih, Whh, Wout, g, kb + 2 * c + 1));
        __half2 hi = __floats2half2_rn(wfold(Wih, Whh, Wout, g, kb + 8 + 2 * c),
                                       wfold(Wih, Whh, Wout, g, kb + 8 + 2 * c + 1));
        uint2 o; o.x = *(uint32_t*)&lo; o.y = *(uint32_t*)&hi;
        g_WimgH[idx] = o;
        if (idx < 512)
            g_bias[idx] = bih[idx] + bhh[idx] + Wih[idx * 64] * bout[0];
    }
}

// Dynamic SMEM (bytes):
//   [0, 196608)        B weight image fp16 (resident all 64 steps)
//   [196608, 221184)   A fragments fp16 (64 rows x 192 k)
//   [221184, 223232)   bias[512] f32
//   [223232, 223744)   Wout[128] f32
//   [223744, 226048)   OACC 64 x 9 f32 (shfl-pre-reduced partials, padded)
#define SMB_TOTAL 226048

__global__ __launch_bounds__(NT, 1)
void lstm_mma(const float* __restrict__ x,  const float* __restrict__ z,
              const float* __restrict__ h0, const float* __restrict__ c0,
              const float* __restrict__ Wout, const float* __restrict__ bout,
              float* __restrict__ Y) {
    extern __shared__ char smem[];
    const uint2* Bs   = (const uint2*)smem;
    __half* A_H       = (__half*)(smem + 196608);
    const uint4* Au   = (const uint4*)(smem + 196608);
    float*  BIASf     = (float*)(smem + 221184);
    float*  WOUTf     = (float*)(smem + 223232);
    float*  OACC      = (float*)(smem + 223744);

    const int tid = threadIdx.x;
    const int half = tid >> 8, t256 = tid & 255;
    const int s = t256 >> 5, lane = tid & 31;      // n-stripe 0..7
    const int tpr = lane >> 2, c = lane & 3;
    const int b0 = blockIdx.x * MR;
    const float bout0 = __ldg(bout);

    // ---- one-time init ----
    {
        uint4* bdst = (uint4*)smem;
        const uint4* bsrc = (const uint4*)g_WimgH;
        for (int e = tid; e < 12288; e += NT) bdst[e] = bsrc[e];   // B -> SMEM once
    }
    for (int e = tid; e < 512; e += NT) BIASf[e] = g_bias[e];
    for (int e = tid; e < 128; e += NT) WOUTf[e] = __ldg(&Wout[e]);
    for (int e = tid; e < MR * 128; e += NT) {          // h0 -> A (k 64..191)
        int row = e >> 7, kk = e & 127;
        A_H[frag_off_h(row, 64 + kk)] = __float2half_rn(h0[(b0 + row) * 128 + kk]);
    }
    for (int e = tid; e < MR * FF; e += NT) {           // z_0 -> A (k 1..63)
        int row = e / FF, f = e - row * FF;
        A_H[frag_off_h(row, 1 + f)] = __float2half_rn(z[((b0 + row) * TT + 64) * FF + f]);
    }
    if (tid < MR) {                                     // delta -> A col 0
        int row = tid;
        float d = x[(b0 + row) * TT + (TT - 1)] - bout0;
        for (int jv = 0; jv < 128; ++jv)
            d -= h0[(b0 + row) * 128 + jv] * __ldg(&Wout[jv]);
        A_H[frag_off_h(row, 0)] = __float2half_rn(d);
    }
    // c-state -> registers: creg[m*8 + j*2 + slot] for row=half*32+m*16+tpr+slot*8, jl=s*16+4j+c
    float creg[16];
    #pragma unroll
    for (int m = 0; m < 2; ++m)
        #pragma unroll
        for (int j = 0; j < 4; ++j)
            #pragma unroll
            for (int slot = 0; slot < 2; ++slot) {
                int row = half * 32 + m * 16 + tpr + slot * 8;
                int jl  = s * 16 + 4 * j + c;
                creg[m * 8 + j * 2 + slot] = c0[(b0 + row) * 128 + jl];
            }
    __syncthreads();

    const int wbase = s * 256 + lane;
    const int mt0 = half * 2, mt1 = half * 2 + 1;

    for (int t = 0; t < PP; ++t) {
        // ---- prefetch z_{t+1} (regs, under the GEMM) ----
        float zreg[8];
        {
            int zrow = half * 32 + (t256 >> 3);
            #pragma unroll
            for (int i = 0; i < 8; ++i) {
                int f = (t256 & 7) * 8 + i;
                zreg[i] = (t < PP - 1 && f < FF)
                        ? z[((b0 + zrow) * TT + 64 + t + 1) * FF + f] : 0.0f;
            }
        }

        // ---- GEMM: D[32,512] per half; B from SMEM (no L2 in the loop) ----
        float acc[2][8][4];
        #pragma unroll
        for (int m = 0; m < 2; ++m)
            #pragma unroll
            for (int j = 0; j < 8; ++j)
                #pragma unroll
                for (int k2 = 0; k2 < 4; ++k2) acc[m][j][k2] = 0.0f;

        #pragma unroll
        for (int ks = 0; ks < 12; ++ks) {
            uint4 a0 = Au[(mt0 * 12 + ks) * 32 + lane];
            uint4 a1 = Au[(mt1 * 12 + ks) * 32 + lane];
            #pragma unroll
            for (int j = 0; j < 8; ++j) {
                uint2 bv = Bs[ks * 2048 + wbase + j * 32];
                mma16(acc[0][j], a0, bv);
                mma16(acc[1][j], a1, bv);
            }
        }
        asm volatile("bar.sync %0, 256;" :: "r"(half + 1) : "memory");  // A reads done

        // ---- epilogue: 4 gates in-thread, c in regs; h -> A ----
        float opart[2][2] = {{0.0f, 0.0f}, {0.0f, 0.0f}};
        #pragma unroll
        for (int m = 0; m < 2; ++m) {
            #pragma unroll
            for (int j = 0; j < 4; ++j) {
                const int jl = s * 16 + 4 * j + c;
                const float bi = BIASf[jl],       bf = BIASf[128 + jl];
                const float bg = BIASf[256 + jl], bo = BIASf[384 + jl];
                const float wj = WOUTf[jl];
                #pragma unroll
                for (int slot = 0; slot < 2; ++slot) {
                    float gi_ = acc[m][j][2 * slot];
                    float gf_ = acc[m][j][2 * slot + 1];
                    float gg_ = acc[m][j + 4][2 * slot];
                    float go_ = acc[m][j + 4][2 * slot + 1];
                    int row = half * 32 + m * 16 + tpr + slot * 8;
                    float i_ = sg_(gi_ + bi), f_ = sg_(gf_ + bf);
                    float g_ = th_(gg_ + bg), o_ = sg_(go_ + bo);
                    float cn = f_ * creg[m * 8 + j * 2 + slot] + i_ * g_;
                    creg[m * 8 + j * 2 + slot] = cn;
                    float hv = o_ * th_(cn);
                    A_H[frag_off_h(row, 64 + jl)] = __float2half_rn(hv);
                    opart[m][slot] += hv * wj;
                }
            }
        }
        // pre-reduce across the c-quad (lanes xor 1, 2), then one store per (warp,row)
        #pragma unroll
        for (int m = 0; m < 2; ++m)
            #pragma unroll
            for (int slot = 0; slot < 2; ++slot) {
                float v = opart[m][slot];
                v += __shfl_xor_sync(0xFFFFFFFFu, v, 1);
                v += __shfl_xor_sync(0xFFFFFFFFu, v, 2);
                if (c == 0) {
                    int row = half * 32 + m * 16 + tpr + slot * 8;
                    OACC[row * 9 + s] = v;
                }
            }

        // z_{t+1} scatter into A cols 1..63
        {
            int zrow = half * 32 + (t256 >> 3);
            #pragma unroll
            for (int i = 0; i < 8; ++i) {
                int f = (t256 & 7) * 8 + i;
                if (f < FF) A_H[frag_off_h(zrow, 1 + f)] = __float2half_rn(zreg[i]);
            }
        }
        if (t == 0 && t256 < 32)     // delta column dies after step 0
            A_H[frag_off_h(half * 32 + t256, 0)] = __float2half_rn(0.0f);
        asm volatile("bar.sync %0, 256;" :: "r"(half + 1) : "memory");  // writes done

        if (t256 < 32) {             // Y: sum 8 stripe partials
            int row = half * 32 + t256;
            const float* p = &OACC[row * 9];
            float ssum = 0.0f;
            #pragma unroll
            for (int u = 0; u < 8; ++u) ssum += p[u];
            Y[(b0 + row) * PP + t] = ssum + bout0;
        }
    }
}

extern "C" void kernel_launch(void* const* d_in, const int* in_sizes, int n_in,
                              void* d_out, int out_size) {
    const float* x    = (const float*)d_in[0];
    const float* z    = (const float*)d_in[1];
    const float* h0   = (const float*)d_in[2];
    const float* c0   = (const float*)d_in[3];
    const float* Wih  = (const float*)d_in[4];
    const float* Whh  = (const float*)d_in[5];
    const float* bih  = (const float*)d_in[6];
    const float* bhh  = (const float*)d_in[7];
    const float* Wout = (const float*)d_in[8];
    const float* bout = (const float*)d_in[9];
    float* Y = (float*)d_out;

    setup_kernel<<<48, 512>>>(Wih, Whh, bih, bhh, Wout, bout);
    cudaFuncSetAttribute(lstm_mma, cudaFuncAttributeMaxDynamicSharedMemorySize, SMB_TOTAL);
    lstm_mma<<<128, NT, SMB_TOTAL>>>(x, z, h0, c0, Wout, bout, Y);
}